// round 4
// baseline (speedup 1.0000x reference)
#include <cuda_runtime.h>
#include <cstdint>

typedef unsigned long long ull;

#define C_DIM 32
#define B_DIM 16
#define N_DIM 1024
#define I_DIM 64
#define O_DIM 32
#define PST   36   // padded priors row stride (floats) in kernel2 smem

// 64 MB scratch for priors (C,B,N,O) fp32
__device__ float g_priors[(size_t)C_DIM * B_DIM * N_DIM * O_DIM];

__device__ __forceinline__ ull pack2(float a, float b) {
    ull r; asm("mov.b64 %0, {%1,%2};" : "=l"(r) : "f"(a), "f"(b)); return r;
}
__device__ __forceinline__ void fma2(ull& d, ull a, ull b) {
    asm("fma.rn.f32x2 %0, %1, %2, %0;" : "+l"(d) : "l"(a), "l"(b));
}
__device__ __forceinline__ float2 unpack2(ull v) {
    float lo, hi; asm("mov.b64 {%0,%1}, %2;" : "=f"(lo), "=f"(hi) : "l"(v));
    return make_float2(lo, hi);
}

// ---------------------------------------------------------------------------
// Kernel 1: priors[c,b,n,o] = sum_i x[b,n,i] * W[c,n,i,o]
// grid (N/8, C), block 256 = 8 warps, warp nl handles n = n0+nl, lane = o.
// W column (64 values) packed into 32 f32x2 regs; x staged in smem,
// read as broadcast LDS.64 i-pairs.
// ---------------------------------------------------------------------------
__global__ __launch_bounds__(256, 1) void priors_kernel(
        const float* __restrict__ x, const float* __restrict__ W) {
    __shared__ __align__(16) float sx[8][16][64];   // [n_local][b][i] 32KB

    const int c  = blockIdx.y;
    const int n0 = blockIdx.x * 8;
    const int t  = threadIdx.x;

    // cooperative, coalesced load of x[:, n0:n0+8, :]
    const float4* xg  = (const float4*)x;
    float4*       sx4 = (float4*)sx;
#pragma unroll
    for (int k = 0; k < 8; k++) {
        int j  = t + k * 256;            // 0..2047
        int i4 = j & 15;
        int b  = (j >> 4) & 15;
        int nl = j >> 8;
        sx4[(nl * 16 + b) * 16 + i4] = xg[((size_t)b * N_DIM + n0 + nl) * 16 + i4];
    }
    __syncthreads();

    const int nl   = t >> 5;
    const int lane = t & 31;
    const int n    = n0 + nl;

    // load W[c,n,:,lane] (coalesced 128B rows), pack i-pairs
    const float* Wc = W + (((size_t)c * N_DIM + n) * I_DIM) * O_DIM + lane;
    ull wd[32];
#pragma unroll
    for (int k = 0; k < 32; k++) {
        float w0 = Wc[(2 * k) * O_DIM];
        float w1 = Wc[(2 * k + 1) * O_DIM];
        wd[k] = pack2(w0, w1);
    }

    float* pout = g_priors + (((size_t)c * B_DIM) * N_DIM + n) * O_DIM + lane;
#pragma unroll 2
    for (int b = 0; b < 16; b++) {
        const ull* xb = (const ull*)(&sx[nl][b][0]);
        ull a0 = 0ull, a1 = 0ull;
#pragma unroll
        for (int k = 0; k < 32; k += 2) {
            fma2(a0, xb[k],     wd[k]);
            fma2(a1, xb[k + 1], wd[k + 1]);
        }
        float2 f0 = unpack2(a0);
        float2 f1 = unpack2(a1);
        pout[(size_t)b * N_DIM * O_DIM] = (f0.x + f0.y) + (f1.x + f1.y);
    }
}

// ---------------------------------------------------------------------------
// Kernel 2: dynamic routing, one block per (c,b). Priors slice staged in smem
// with padded stride 36 floats (conflict-free for both access patterns).
// ---------------------------------------------------------------------------
__global__ __launch_bounds__(256, 1) void routing_kernel(float* __restrict__ out) {
    extern __shared__ __align__(16) float sm[];
    float* P      = sm;                     // 1024*36
    float* logits = P + N_DIM * PST;        // 1024
    float* probs  = logits + N_DIM;         // 1024
    float* red    = probs + N_DIM;          // 256
    float* outv   = red + 256;              // 32 (16B aligned)

    const int cb   = blockIdx.x;
    const int t    = threadIdx.x;
    const int lane = t & 31;
    const int wid  = t >> 5;

    // stage priors[cb] into padded smem
    const float4* gp = (const float4*)(g_priors + (size_t)cb * N_DIM * O_DIM);
    float4*       P4 = (float4*)P;
#pragma unroll
    for (int k = 0; k < 32; k++) {
        int j  = t + k * 256;               // 0..8191
        int o4 = j & 7;
        int n  = j >> 3;
        P4[n * 9 + o4] = gp[j];
    }
    __syncthreads();

    // ---- iteration 1: probs uniform = 1/N ----
    {
        float acc = 0.f;
        for (int n = wid; n < N_DIM; n += 8)
            acc += P[n * PST + lane];
        red[t] = acc;
        __syncthreads();
        if (t < 32) {
            float v = 0.f;
#pragma unroll
            for (int g = 0; g < 8; g++) v += red[g * 32 + t];
            v *= (1.f / N_DIM);
            float sq = v * v;
#pragma unroll
            for (int off = 16; off; off >>= 1)
                sq += __shfl_xor_sync(0xffffffffu, sq, off);
            outv[t] = v * (sqrtf(sq) / (1.f + sq));
        }
        __syncthreads();
    }

    // ---- iterations 2 and 3 ----
    for (int it = 0; it < 2; it++) {
        float4 ov[8];
        const float4* ovp = (const float4*)outv;
#pragma unroll
        for (int j = 0; j < 8; j++) ov[j] = ovp[j];

        // delta[n] = P[n,:] . out ; update logits; track max
        float l[4];
        float mymax = -1e30f;
#pragma unroll
        for (int k = 0; k < 4; k++) {
            int n = t + k * 256;
            const float4* pn = (const float4*)(P + n * PST);
            float d = 0.f;
#pragma unroll
            for (int j = 0; j < 8; j++) {
                float4 pv = pn[j];
                d += pv.x * ov[j].x + pv.y * ov[j].y + pv.z * ov[j].z + pv.w * ov[j].w;
            }
            float lv = (it == 0) ? d : (logits[n] + d);
            logits[n] = lv;
            l[k]      = lv;
            mymax     = fmaxf(mymax, lv);
        }
#pragma unroll
        for (int off = 16; off; off >>= 1)
            mymax = fmaxf(mymax, __shfl_xor_sync(0xffffffffu, mymax, off));
        if (lane == 0) red[wid] = mymax;
        __syncthreads();
        float bmax = red[0];
#pragma unroll
        for (int g = 1; g < 8; g++) bmax = fmaxf(bmax, red[g]);
        __syncthreads();

        // exp + sum
        float mysum = 0.f;
#pragma unroll
        for (int k = 0; k < 4; k++) {
            int n   = t + k * 256;
            float e = __expf(l[k] - bmax);
            probs[n] = e;
            mysum   += e;
        }
#pragma unroll
        for (int off = 16; off; off >>= 1)
            mysum += __shfl_xor_sync(0xffffffffu, mysum, off);
        if (lane == 0) red[wid] = mysum;
        __syncthreads();
        float Z = 0.f;
#pragma unroll
        for (int g = 0; g < 8; g++) Z += red[g];
        float inv = 1.f / Z;
        __syncthreads();

        // s[o] = sum_n probs[n] * P[n,o] ; squash
        float acc = 0.f;
        for (int n = wid; n < N_DIM; n += 8)
            acc += probs[n] * P[n * PST + lane];
        red[t] = acc;
        __syncthreads();
        if (t < 32) {
            float v = 0.f;
#pragma unroll
            for (int g = 0; g < 8; g++) v += red[g * 32 + t];
            v *= inv;
            float sq = v * v;
#pragma unroll
            for (int off = 16; off; off >>= 1)
                sq += __shfl_xor_sync(0xffffffffu, sq, off);
            outv[t] = v * (sqrtf(sq) / (1.f + sq));
        }
        __syncthreads();
    }

    if (t < 32) out[cb * O_DIM + t] = outv[t];
}

// ---------------------------------------------------------------------------
extern "C" void kernel_launch(void* const* d_in, const int* in_sizes, int n_in,
                              void* d_out, int out_size) {
    const float* x = (const float*)d_in[0];
    const float* W = (const float*)d_in[1];
    if (n_in >= 2 && in_sizes[0] > in_sizes[1]) {  // defensive input ordering
        x = (const float*)d_in[1];
        W = (const float*)d_in[0];
    }

    const int SMEM2 = (N_DIM * PST + N_DIM + N_DIM + 256 + 32) * 4;  // 156800 B
    cudaFuncSetAttribute(routing_kernel,
                         cudaFuncAttributeMaxDynamicSharedMemorySize, SMEM2);

    priors_kernel<<<dim3(N_DIM / 8, C_DIM), 256>>>(x, W);
    routing_kernel<<<C_DIM * B_DIM, 256, SMEM2>>>((float*)d_out);
}

// round 6
// speedup vs baseline: 1.2266x; 1.2266x over previous
#include <cuda_runtime.h>
#include <cstdint>

typedef unsigned long long ull;

#define C_DIM 32
#define B_DIM 16
#define N_DIM 1024
#define I_DIM 64
#define O_DIM 32
#define PST   36   // padded priors row stride (floats) in kernel2 smem

// 64 MB scratch for priors (C,B,N,O) fp32
__device__ __align__(256) float g_priors[(size_t)C_DIM * B_DIM * N_DIM * O_DIM];

__device__ __forceinline__ ull pack2(float a, float b) {
    ull r; asm("mov.b64 %0, {%1,%2};" : "=l"(r) : "f"(a), "f"(b)); return r;
}
__device__ __forceinline__ void fma2(ull& d, ull a, ull b) {
    asm("fma.rn.f32x2 %0, %1, %2, %0;" : "+l"(d) : "l"(a), "l"(b));
}
__device__ __forceinline__ float2 unpack2(ull v) {
    float lo, hi; asm("mov.b64 {%0,%1}, %2;" : "=f"(lo), "=f"(hi) : "l"(v));
    return make_float2(lo, hi);
}

// ---------------------------------------------------------------------------
// Kernel 1: priors[c,b,n,o] = sum_i x[b,n,i] * W[c,n,i,o]
// grid (N/8, C), block 256 = 8 warps, warp nl handles n = n0+nl, lane = o.
// W column (64 values) packed into 32 f32x2 regs; x staged in smem,
// read as broadcast LDS.64 i-pairs. minBlocks=2 forces regs<=128 so two
// CTAs co-reside: one CTA's W DRAM stream overlaps the other's FFMA2 phase.
// ---------------------------------------------------------------------------
__global__ __launch_bounds__(256, 2) void priors_kernel(
        const float* __restrict__ x, const float* __restrict__ W) {
    __shared__ __align__(16) float sx[8][16][64];   // [n_local][b][i] 32KB

    const int c  = blockIdx.y;
    const int n0 = blockIdx.x * 8;
    const int t  = threadIdx.x;

    // cooperative, coalesced load of x[:, n0:n0+8, :]
    const float4* xg  = (const float4*)x;
    float4*       sx4 = (float4*)sx;
#pragma unroll
    for (int k = 0; k < 8; k++) {
        int j  = t + k * 256;            // 0..2047
        int i4 = j & 15;
        int b  = (j >> 4) & 15;
        int nl = j >> 8;
        sx4[(nl * 16 + b) * 16 + i4] = xg[((size_t)b * N_DIM + n0 + nl) * 16 + i4];
    }
    __syncthreads();

    const int nl   = t >> 5;
    const int lane = t & 31;
    const int n    = n0 + nl;

    // load W[c,n,:,lane] (coalesced 128B rows), pack i-pairs
    const float* Wc = W + (((size_t)c * N_DIM + n) * I_DIM) * O_DIM + lane;
    ull wd[32];
#pragma unroll
    for (int k = 0; k < 32; k++) {
        float w0 = Wc[(2 * k) * O_DIM];
        float w1 = Wc[(2 * k + 1) * O_DIM];
        wd[k] = pack2(w0, w1);
    }

    float* pout = g_priors + (((size_t)c * B_DIM) * N_DIM + n) * O_DIM + lane;
#pragma unroll 2
    for (int b = 0; b < 16; b++) {
        const ull* xb = (const ull*)(&sx[nl][b][0]);
        ull a0 = 0ull, a1 = 0ull;
#pragma unroll
        for (int k = 0; k < 32; k += 2) {
            fma2(a0, xb[k],     wd[k]);
            fma2(a1, xb[k + 1], wd[k + 1]);
        }
        float2 f0 = unpack2(a0);
        float2 f1 = unpack2(a1);
        pout[(size_t)b * N_DIM * O_DIM] = (f0.x + f0.y) + (f1.x + f1.y);
    }
}

// ---------------------------------------------------------------------------
// Kernel 2: dynamic routing, one block per (c,b), 512 threads (16 warps) for
// latency hiding. Priors slice staged in smem fp32, padded stride 36 floats
// (conflict-free for both row-major float4 reads and per-column reductions).
// ---------------------------------------------------------------------------
__global__ __launch_bounds__(512, 1) void routing_kernel(float* __restrict__ out) {
    extern __shared__ __align__(16) float sm[];
    float* P      = sm;                     // 1024*36 = 144KB
    float* logits = P + N_DIM * PST;        // 1024
    float* probs  = logits + N_DIM;         // 1024
    float* red    = probs + N_DIM;          // 512
    float* outv   = red + 512;              // 32 (16B aligned)

    const int cb   = blockIdx.x;
    const int t    = threadIdx.x;
    const int lane = t & 31;
    const int wid  = t >> 5;                // 0..15

    // stage priors[cb] into padded smem: 8192 float4, 16 per thread
    const float4* gp = (const float4*)(g_priors + (size_t)cb * N_DIM * O_DIM);
    float4*       P4 = (float4*)P;
#pragma unroll
    for (int k = 0; k < 16; k++) {
        int j  = t + k * 512;               // 0..8191
        int o4 = j & 7;
        int n  = j >> 3;
        P4[n * 9 + o4] = gp[j];
    }
    __syncthreads();

    // ---- iteration 1: probs uniform = 1/N ----
    {
        float a0 = 0.f, a1 = 0.f;
        for (int n = wid; n < N_DIM; n += 32) {
            a0 += P[n * PST + lane];
            a1 += P[(n + 16) * PST + lane];
        }
        red[t] = a0 + a1;
        __syncthreads();
        if (t < 32) {
            float v = 0.f;
#pragma unroll
            for (int g = 0; g < 16; g++) v += red[g * 32 + t];
            v *= (1.f / N_DIM);
            float sq = v * v;
#pragma unroll
            for (int off = 16; off; off >>= 1)
                sq += __shfl_xor_sync(0xffffffffu, sq, off);
            outv[t] = v * (sqrtf(sq) / (1.f + sq));
        }
        __syncthreads();
    }

    // ---- iterations 2 and 3 ----
    for (int it = 0; it < 2; it++) {
        float4 ov[8];
        const float4* ovp = (const float4*)outv;
#pragma unroll
        for (int j = 0; j < 8; j++) ov[j] = ovp[j];

        // delta[n] = P[n,:] . out ; update logits; track max
        float l[2];
        float mymax = -1e30f;
#pragma unroll
        for (int k = 0; k < 2; k++) {
            int n = t + k * 512;
            const float4* pn = (const float4*)(P + n * PST);
            float d = 0.f;
#pragma unroll
            for (int j = 0; j < 8; j++) {
                float4 pv = pn[j];
                d += pv.x * ov[j].x + pv.y * ov[j].y + pv.z * ov[j].z + pv.w * ov[j].w;
            }
            float lv = (it == 0) ? d : (logits[n] + d);
            logits[n] = lv;
            l[k]      = lv;
            mymax     = fmaxf(mymax, lv);
        }
#pragma unroll
        for (int off = 16; off; off >>= 1)
            mymax = fmaxf(mymax, __shfl_xor_sync(0xffffffffu, mymax, off));
        if (lane == 0) red[wid] = mymax;
        __syncthreads();
        float bmax = red[0];
#pragma unroll
        for (int g = 1; g < 16; g++) bmax = fmaxf(bmax, red[g]);
        __syncthreads();

        // exp + sum
        float mysum = 0.f;
#pragma unroll
        for (int k = 0; k < 2; k++) {
            int n   = t + k * 512;
            float e = __expf(l[k] - bmax);
            probs[n] = e;
            mysum   += e;
        }
#pragma unroll
        for (int off = 16; off; off >>= 1)
            mysum += __shfl_xor_sync(0xffffffffu, mysum, off);
        if (lane == 0) red[wid] = mysum;
        __syncthreads();
        float Z = 0.f;
#pragma unroll
        for (int g = 0; g < 16; g++) Z += red[g];
        float inv = 1.f / Z;
        __syncthreads();

        // s[o] = sum_n probs[n] * P[n,o] ; squash
        float a0 = 0.f, a1 = 0.f;
        for (int n = wid; n < N_DIM; n += 32) {
            a0 += probs[n] * P[n * PST + lane];
            a1 += probs[n + 16] * P[(n + 16) * PST + lane];
        }
        red[t] = a0 + a1;
        __syncthreads();
        if (t < 32) {
            float v = 0.f;
#pragma unroll
            for (int g = 0; g < 16; g++) v += red[g * 32 + t];
            v *= inv;
            float sq = v * v;
#pragma unroll
            for (int off = 16; off; off >>= 1)
                sq += __shfl_xor_sync(0xffffffffu, sq, off);
            outv[t] = v * (sqrtf(sq) / (1.f + sq));
        }
        __syncthreads();
    }

    if (t < 32) out[cb * O_DIM + t] = outv[t];
}

// ---------------------------------------------------------------------------
extern "C" void kernel_launch(void* const* d_in, const int* in_sizes, int n_in,
                              void* d_out, int out_size) {
    const float* x = (const float*)d_in[0];
    const float* W = (const float*)d_in[1];
    if (n_in >= 2 && in_sizes[0] > in_sizes[1]) {  // defensive input ordering
        x = (const float*)d_in[1];
        W = (const float*)d_in[0];
    }

    // P (144KB) + logits/probs (8KB) + red (2KB) + outv (128B)
    const int SMEM2 = (N_DIM * PST + N_DIM + N_DIM + 512 + 32) * 4;  // 157824 B
    cudaFuncSetAttribute(routing_kernel,
                         cudaFuncAttributeMaxDynamicSharedMemorySize, SMEM2);

    priors_kernel<<<dim3(N_DIM / 8, C_DIM), 256>>>(x, W);
    routing_kernel<<<C_DIM * B_DIM, 512, SMEM2>>>((float*)d_out);
}

// round 7
// speedup vs baseline: 1.2494x; 1.0186x over previous
#include <cuda_runtime.h>
#include <cstdint>

typedef unsigned long long ull;

#define C_DIM 32
#define B_DIM 16
#define N_DIM 1024
#define I_DIM 64
#define O_DIM 32
#define PST   36   // padded priors row stride (floats) in kernel2 smem

// 64 MB scratch for priors (C,B,N,O) fp32
__device__ __align__(256) float g_priors[(size_t)C_DIM * B_DIM * N_DIM * O_DIM];

__device__ __forceinline__ ull pack2(float a, float b) {
    ull r; asm("mov.b64 %0, {%1,%2};" : "=l"(r) : "f"(a), "f"(b)); return r;
}
__device__ __forceinline__ void fma2(ull& d, ull a, ull b) {
    asm("fma.rn.f32x2 %0, %1, %2, %0;" : "+l"(d) : "l"(a), "l"(b));
}
__device__ __forceinline__ float2 unpack2(ull v) {
    float lo, hi; asm("mov.b64 {%0,%1}, %2;" : "=f"(lo), "=f"(hi) : "l"(v));
    return make_float2(lo, hi);
}

// ---------------------------------------------------------------------------
// Kernel 1: priors[c,b,n,o] = sum_i x[b,n,i] * W[c,n,i,o]
// grid (N/8, C), block 256 = 8 warps, warp nl handles n = n0+nl, lane = o.
// W streamed in 4 chunks of 16 i-values (16 LDG each, pipelined against the
// previous chunk's FMAs); per-b f32x2 accumulators persist across chunks.
// ~70 regs -> 3 CTAs/SM for continuous DRAM streaming. W/priors use
// streaming cache hints (single-use); x stays cached (reused by 32 c-blocks).
// ---------------------------------------------------------------------------
__global__ __launch_bounds__(256, 3) void priors_kernel(
        const float* __restrict__ x, const float* __restrict__ W) {
    __shared__ __align__(16) float sx[8][16][64];   // [n_local][b][i] 32KB

    const int c  = blockIdx.y;
    const int n0 = blockIdx.x * 8;
    const int t  = threadIdx.x;

    // cooperative, coalesced load of x[:, n0:n0+8, :]
    const float4* xg  = (const float4*)x;
    float4*       sx4 = (float4*)sx;
#pragma unroll
    for (int k = 0; k < 8; k++) {
        int j  = t + k * 256;            // 0..2047
        int i4 = j & 15;
        int b  = (j >> 4) & 15;
        int nl = j >> 8;
        sx4[(nl * 16 + b) * 16 + i4] = xg[((size_t)b * N_DIM + n0 + nl) * 16 + i4];
    }
    __syncthreads();

    const int nl   = t >> 5;
    const int lane = t & 31;
    const int n    = n0 + nl;

    const float* Wc = W + (((size_t)c * N_DIM + n) * I_DIM) * O_DIM + lane;

    ull acc[16];
#pragma unroll
    for (int b = 0; b < 16; b++) acc[b] = 0ull;

#pragma unroll
    for (int h = 0; h < 4; h++) {
        // load W chunk: i in [16h, 16h+16), packed as 8 i-pairs
        ull wd[8];
#pragma unroll
        for (int j = 0; j < 8; j++) {
            float w0 = __ldcs(Wc + (h * 16 + 2 * j)     * O_DIM);
            float w1 = __ldcs(Wc + (h * 16 + 2 * j + 1) * O_DIM);
            wd[j] = pack2(w0, w1);
        }
#pragma unroll
        for (int b = 0; b < 16; b++) {
            const ulonglong2* xb = (const ulonglong2*)(&sx[nl][b][h * 16]);
#pragma unroll
            for (int q = 0; q < 4; q++) {
                ulonglong2 xv = xb[q];          // LDS.128 broadcast: 4 x-values
                fma2(acc[b], xv.x, wd[2 * q]);
                fma2(acc[b], xv.y, wd[2 * q + 1]);
            }
        }
    }

    float* pout = g_priors + (((size_t)c * B_DIM) * N_DIM + n) * O_DIM + lane;
#pragma unroll
    for (int b = 0; b < 16; b++) {
        float2 f = unpack2(acc[b]);
        __stcs(pout + (size_t)b * N_DIM * O_DIM, f.x + f.y);
    }
}

// ---------------------------------------------------------------------------
// Kernel 2: dynamic routing, one block per (c,b), 512 threads (16 warps).
// Priors slice staged in smem fp32, padded stride 36 floats (conflict-free
// for both row-major float4 reads and per-column reductions).
// ---------------------------------------------------------------------------
__global__ __launch_bounds__(512, 1) void routing_kernel(float* __restrict__ out) {
    extern __shared__ __align__(16) float sm[];
    float* P      = sm;                     // 1024*36 = 144KB
    float* logits = P + N_DIM * PST;        // 1024
    float* probs  = logits + N_DIM;         // 1024
    float* red    = probs + N_DIM;          // 512
    float* outv   = red + 512;              // 32 (16B aligned)

    const int cb   = blockIdx.x;
    const int t    = threadIdx.x;
    const int lane = t & 31;
    const int wid  = t >> 5;                // 0..15

    // stage priors[cb] into padded smem: 8192 float4, 16 per thread
    const float4* gp = (const float4*)(g_priors + (size_t)cb * N_DIM * O_DIM);
    float4*       P4 = (float4*)P;
#pragma unroll
    for (int k = 0; k < 16; k++) {
        int j  = t + k * 512;               // 0..8191
        int o4 = j & 7;
        int n  = j >> 3;
        P4[n * 9 + o4] = gp[j];
    }
    __syncthreads();

    // ---- iteration 1: probs uniform = 1/N ----
    {
        float a0 = 0.f, a1 = 0.f;
        for (int n = wid; n < N_DIM; n += 32) {
            a0 += P[n * PST + lane];
            a1 += P[(n + 16) * PST + lane];
        }
        red[t] = a0 + a1;
        __syncthreads();
        if (t < 32) {
            float v = 0.f;
#pragma unroll
            for (int g = 0; g < 16; g++) v += red[g * 32 + t];
            v *= (1.f / N_DIM);
            float sq = v * v;
#pragma unroll
            for (int off = 16; off; off >>= 1)
                sq += __shfl_xor_sync(0xffffffffu, sq, off);
            outv[t] = v * (sqrtf(sq) / (1.f + sq));
        }
        __syncthreads();
    }

    // ---- iterations 2 and 3 ----
    for (int it = 0; it < 2; it++) {
        float4 ov[8];
        const float4* ovp = (const float4*)outv;
#pragma unroll
        for (int j = 0; j < 8; j++) ov[j] = ovp[j];

        // delta[n] = P[n,:] . out ; update logits; track max
        float l[2];
        float mymax = -1e30f;
#pragma unroll
        for (int k = 0; k < 2; k++) {
            int n = t + k * 512;
            const float4* pn = (const float4*)(P + n * PST);
            float d = 0.f;
#pragma unroll
            for (int j = 0; j < 8; j++) {
                float4 pv = pn[j];
                d += pv.x * ov[j].x + pv.y * ov[j].y + pv.z * ov[j].z + pv.w * ov[j].w;
            }
            float lv = (it == 0) ? d : (logits[n] + d);
            logits[n] = lv;
            l[k]      = lv;
            mymax     = fmaxf(mymax, lv);
        }
#pragma unroll
        for (int off = 16; off; off >>= 1)
            mymax = fmaxf(mymax, __shfl_xor_sync(0xffffffffu, mymax, off));
        if (lane == 0) red[wid] = mymax;
        __syncthreads();
        float bmax = red[0];
#pragma unroll
        for (int g = 1; g < 16; g++) bmax = fmaxf(bmax, red[g]);
        __syncthreads();

        // exp + sum
        float mysum = 0.f;
#pragma unroll
        for (int k = 0; k < 2; k++) {
            int n   = t + k * 512;
            float e = __expf(l[k] - bmax);
            probs[n] = e;
            mysum   += e;
        }
#pragma unroll
        for (int off = 16; off; off >>= 1)
            mysum += __shfl_xor_sync(0xffffffffu, mysum, off);
        if (lane == 0) red[wid] = mysum;
        __syncthreads();
        float Z = 0.f;
#pragma unroll
        for (int g = 0; g < 16; g++) Z += red[g];
        float inv = 1.f / Z;
        __syncthreads();

        // s[o] = sum_n probs[n] * P[n,o] ; squash
        float a0 = 0.f, a1 = 0.f;
        for (int n = wid; n < N_DIM; n += 32) {
            a0 += probs[n] * P[n * PST + lane];
            a1 += probs[n + 16] * P[(n + 16) * PST + lane];
        }
        red[t] = a0 + a1;
        __syncthreads();
        if (t < 32) {
            float v = 0.f;
#pragma unroll
            for (int g = 0; g < 16; g++) v += red[g * 32 + t];
            v *= inv;
            float sq = v * v;
#pragma unroll
            for (int off = 16; off; off >>= 1)
                sq += __shfl_xor_sync(0xffffffffu, sq, off);
            outv[t] = v * (sqrtf(sq) / (1.f + sq));
        }
        __syncthreads();
    }

    if (t < 32) out[cb * O_DIM + t] = outv[t];
}

// ---------------------------------------------------------------------------
extern "C" void kernel_launch(void* const* d_in, const int* in_sizes, int n_in,
                              void* d_out, int out_size) {
    const float* x = (const float*)d_in[0];
    const float* W = (const float*)d_in[1];
    if (n_in >= 2 && in_sizes[0] > in_sizes[1]) {  // defensive input ordering
        x = (const float*)d_in[1];
        W = (const float*)d_in[0];
    }

    // P (144KB) + logits/probs (8KB) + red (2KB) + outv (128B)
    const int SMEM2 = (N_DIM * PST + N_DIM + N_DIM + 512 + 32) * 4;  // 157824 B
    cudaFuncSetAttribute(routing_kernel,
                         cudaFuncAttributeMaxDynamicSharedMemorySize, SMEM2);

    priors_kernel<<<dim3(N_DIM / 8, C_DIM), 256>>>(x, W);
    routing_kernel<<<C_DIM * B_DIM, 512, SMEM2>>>((float*)d_out);
}

// round 9
// speedup vs baseline: 1.3274x; 1.0625x over previous
#include <cuda_runtime.h>
#include <cstdint>

typedef unsigned long long ull;

#define C_DIM 32
#define B_DIM 16
#define N_DIM 1024
#define I_DIM 64
#define O_DIM 32
#define CB    (C_DIM * B_DIM)

// 64 MB scratch for priors (C,B,N,O) fp32  (kept L2-resident for routing passes)
__device__ __align__(256) float g_priors[(size_t)C_DIM * B_DIM * N_DIM * O_DIM];
__device__ __align__(16)  float g_out1[CB * O_DIM];
__device__ __align__(16)  float g_out2[CB * O_DIM];

__device__ __forceinline__ ull pack2(float a, float b) {
    ull r; asm("mov.b64 %0, {%1,%2};" : "=l"(r) : "f"(a), "f"(b)); return r;
}
__device__ __forceinline__ void fma2(ull& d, ull a, ull b) {
    asm("fma.rn.f32x2 %0, %1, %2, %0;" : "+l"(d) : "l"(a), "l"(b));
}
__device__ __forceinline__ float2 unpack2(ull v) {
    float lo, hi; asm("mov.b64 {%0,%1}, %2;" : "=f"(lo), "=f"(hi) : "l"(v));
    return make_float2(lo, hi);
}

// ---------------------------------------------------------------------------
// Kernel 1: priors[c,b,n,o] = sum_i x[b,n,i] * W[c,n,i,o]
// grid (N/8, C), block 256 = 8 warps, warp nl handles n = n0+nl, lane = o.
// W streamed (evict-first, single use); priors stored with DEFAULT policy so
// the 64MB scratch stays L2-resident for the routing passes.
// ---------------------------------------------------------------------------
__global__ __launch_bounds__(256, 3) void priors_kernel(
        const float* __restrict__ x, const float* __restrict__ W) {
    __shared__ __align__(16) float sx[8][16][64];   // [n_local][b][i] 32KB

    const int c  = blockIdx.y;
    const int n0 = blockIdx.x * 8;
    const int t  = threadIdx.x;

    const float4* xg  = (const float4*)x;
    float4*       sx4 = (float4*)sx;
#pragma unroll
    for (int k = 0; k < 8; k++) {
        int j  = t + k * 256;            // 0..2047
        int i4 = j & 15;
        int b  = (j >> 4) & 15;
        int nl = j >> 8;
        sx4[(nl * 16 + b) * 16 + i4] = xg[((size_t)b * N_DIM + n0 + nl) * 16 + i4];
    }
    __syncthreads();

    const int nl   = t >> 5;
    const int lane = t & 31;
    const int n    = n0 + nl;

    const float* Wc = W + (((size_t)c * N_DIM + n) * I_DIM) * O_DIM + lane;

    ull acc[16];
#pragma unroll
    for (int b = 0; b < 16; b++) acc[b] = 0ull;

#pragma unroll
    for (int h = 0; h < 4; h++) {
        ull wd[8];
#pragma unroll
        for (int j = 0; j < 8; j++) {
            float w0 = __ldcs(Wc + (h * 16 + 2 * j)     * O_DIM);
            float w1 = __ldcs(Wc + (h * 16 + 2 * j + 1) * O_DIM);
            wd[j] = pack2(w0, w1);
        }
#pragma unroll
        for (int b = 0; b < 16; b++) {
            const ulonglong2* xb = (const ulonglong2*)(&sx[nl][b][h * 16]);
#pragma unroll
            for (int q = 0; q < 4; q++) {
                ulonglong2 xv = xb[q];
                fma2(acc[b], xv.x, wd[2 * q]);
                fma2(acc[b], xv.y, wd[2 * q + 1]);
            }
        }
    }

    float* pout = g_priors + (((size_t)c * B_DIM) * N_DIM + n) * O_DIM + lane;
#pragma unroll
    for (int b = 0; b < 16; b++) {
        float2 f = unpack2(acc[b]);
        pout[(size_t)b * N_DIM * O_DIM] = f.x + f.y;   // default policy: stay in L2
    }
}

// ---------------------------------------------------------------------------
// Routing pass 1: out1[cb,:] = squash( (1/N) * sum_n P[cb,n,:] )
// 512 blocks x 256 threads. Warp loads 4 rows/round (coalesced float4,
// 8 lanes per 128B row), 32 rounds.
// ---------------------------------------------------------------------------
__global__ __launch_bounds__(256) void route_pass1() {
    __shared__ float red[8][32];
    const int cb = blockIdx.x;
    const int t  = threadIdx.x;
    const int l  = t & 31;
    const int w  = t >> 5;
    const int sub = l >> 3;      // row within 4-row group
    const int o4  = l & 7;       // which float4 of the row

    const float* base = g_priors + (size_t)cb * N_DIM * O_DIM;
    float4 acc = make_float4(0.f, 0.f, 0.f, 0.f);
#pragma unroll 4
    for (int r = 0; r < 32; r++) {
        int n = r * 32 + w * 4 + sub;
        float4 p = *(const float4*)(base + n * O_DIM + o4 * 4);
        acc.x += p.x; acc.y += p.y; acc.z += p.z; acc.w += p.w;
    }
    // reduce over the 4 row-subgroups (lanes xor 8, 16)
#pragma unroll
    for (int off = 8; off <= 16; off <<= 1) {
        acc.x += __shfl_xor_sync(~0u, acc.x, off);
        acc.y += __shfl_xor_sync(~0u, acc.y, off);
        acc.z += __shfl_xor_sync(~0u, acc.z, off);
        acc.w += __shfl_xor_sync(~0u, acc.w, off);
    }
    if (l < 8) {
        red[w][o4 * 4 + 0] = acc.x;
        red[w][o4 * 4 + 1] = acc.y;
        red[w][o4 * 4 + 2] = acc.z;
        red[w][o4 * 4 + 3] = acc.w;
    }
    __syncthreads();
    if (t < 32) {
        float v = 0.f;
#pragma unroll
        for (int g = 0; g < 8; g++) v += red[g][t];
        v *= (1.f / N_DIM);
        float sq = v * v;
#pragma unroll
        for (int off = 16; off; off >>= 1)
            sq += __shfl_xor_sync(~0u, sq, off);
        g_out1[cb * O_DIM + t] = v * (sqrtf(sq) / (1.f + sq));
    }
}

// ---------------------------------------------------------------------------
// Routing passes 2/3: online softmax over n with score vector wv,
// outv = squash( sum_n softmax(P·wv)[n] * P[n,:] ).
// ADD_W2: wv = out1 + out2 (iter 3, logits linear in P); else wv = out1.
// ---------------------------------------------------------------------------
template <bool ADD_W2>
__global__ __launch_bounds__(256) void route_online(float* __restrict__ dst) {
    __shared__ float sm_w[32];
    __shared__ float sm_m[8], sm_z[8];
    __shared__ float sm_acc[8][32];

    const int cb = blockIdx.x;
    const int t  = threadIdx.x;
    const int l  = t & 31;
    const int w  = t >> 5;
    const int sub = l >> 3;
    const int o4  = l & 7;

    if (t < 32) {
        float wv = g_out1[cb * O_DIM + t];
        if (ADD_W2) wv += g_out2[cb * O_DIM + t];
        sm_w[t] = wv;
    }
    __syncthreads();

    float4 w4 = *(const float4*)(sm_w + o4 * 4);

    const float* base = g_priors + (size_t)cb * N_DIM * O_DIM;
    float  m = -3.0e38f, Z = 0.f;
    float4 acc = make_float4(0.f, 0.f, 0.f, 0.f);

#pragma unroll 4
    for (int r = 0; r < 32; r++) {
        int n = r * 32 + w * 4 + sub;
        float4 p = *(const float4*)(base + n * O_DIM + o4 * 4);
        float d = p.x * w4.x + p.y * w4.y + p.z * w4.z + p.w * w4.w;
        d += __shfl_xor_sync(~0u, d, 4);
        d += __shfl_xor_sync(~0u, d, 2);
        d += __shfl_xor_sync(~0u, d, 1);     // all 8 row-lanes hold full dot
        float mn = fmaxf(m, d);
        float sc = __expf(m - mn);
        float e  = __expf(d - mn);
        Z = Z * sc + e;
        acc.x = acc.x * sc + e * p.x;
        acc.y = acc.y * sc + e * p.y;
        acc.z = acc.z * sc + e * p.z;
        acc.w = acc.w * sc + e * p.w;
        m = mn;
    }

    // merge the 4 row-subgroups (lanes xor 8, 16)
#pragma unroll
    for (int off = 8; off <= 16; off <<= 1) {
        float m2 = __shfl_xor_sync(~0u, m, off);
        float Z2 = __shfl_xor_sync(~0u, Z, off);
        float ax = __shfl_xor_sync(~0u, acc.x, off);
        float ay = __shfl_xor_sync(~0u, acc.y, off);
        float az = __shfl_xor_sync(~0u, acc.z, off);
        float aw = __shfl_xor_sync(~0u, acc.w, off);
        float M  = fmaxf(m, m2);
        float s1 = __expf(m  - M);
        float s2 = __expf(m2 - M);
        Z = Z * s1 + Z2 * s2;
        acc.x = acc.x * s1 + ax * s2;
        acc.y = acc.y * s1 + ay * s2;
        acc.z = acc.z * s1 + az * s2;
        acc.w = acc.w * s1 + aw * s2;
        m = M;
    }
    if (l == 0) { sm_m[w] = m; sm_z[w] = Z; }
    if (l < 8) {
        sm_acc[w][o4 * 4 + 0] = acc.x;
        sm_acc[w][o4 * 4 + 1] = acc.y;
        sm_acc[w][o4 * 4 + 2] = acc.z;
        sm_acc[w][o4 * 4 + 3] = acc.w;
    }
    __syncthreads();

    if (t < 32) {
        float M = sm_m[0];
#pragma unroll
        for (int g = 1; g < 8; g++) M = fmaxf(M, sm_m[g]);
        float Zt = 0.f, st = 0.f;
#pragma unroll
        for (int g = 0; g < 8; g++) {
            float f = __expf(sm_m[g] - M);
            Zt += sm_z[g] * f;
            st += sm_acc[g][t] * f;
        }
        float v = st / Zt;
        float sq = v * v;
#pragma unroll
        for (int off = 16; off; off >>= 1)
            sq += __shfl_xor_sync(~0u, sq, off);
        dst[cb * O_DIM + t] = v * (sqrtf(sq) / (1.f + sq));
    }
}

// ---------------------------------------------------------------------------
extern "C" void kernel_launch(void* const* d_in, const int* in_sizes, int n_in,
                              void* d_out, int out_size) {
    const float* x = (const float*)d_in[0];
    const float* W = (const float*)d_in[1];
    if (n_in >= 2 && in_sizes[0] > in_sizes[1]) {  // defensive input ordering
        x = (const float*)d_in[1];
        W = (const float*)d_in[0];
    }

    priors_kernel<<<dim3(N_DIM / 8, C_DIM), 256>>>(x, W);
    route_pass1<<<CB, 256>>>();
    float* out2p;
    cudaGetSymbolAddress((void**)&out2p, g_out2);
    route_online<false><<<CB, 256>>>(out2p);
    route_online<true><<<CB, 256>>>((float*)d_out);
}

// round 10
// speedup vs baseline: 1.3278x; 1.0003x over previous
#include <cuda_runtime.h>
#include <cstdint>

typedef unsigned long long ull;

#define C_DIM 32
#define B_DIM 16
#define N_DIM 1024
#define I_DIM 64
#define O_DIM 32
#define CB    (C_DIM * B_DIM)

// 64 MB scratch for priors (C,B,N,O) fp32
__device__ __align__(256) float g_priors[(size_t)C_DIM * B_DIM * N_DIM * O_DIM];

__device__ __forceinline__ ull pack2(float a, float b) {
    ull r; asm("mov.b64 %0, {%1,%2};" : "=l"(r) : "f"(a), "f"(b)); return r;
}
__device__ __forceinline__ void fma2(ull& d, ull a, ull b) {
    asm("fma.rn.f32x2 %0, %1, %2, %0;" : "+l"(d) : "l"(a), "l"(b));
}
__device__ __forceinline__ float2 unpack2(ull v) {
    float lo, hi; asm("mov.b64 {%0,%1}, %2;" : "=f"(lo), "=f"(hi) : "l"(v));
    return make_float2(lo, hi);
}

// ---------------------------------------------------------------------------
// Kernel 1 (unchanged from R9): priors[c,b,n,o] = sum_i x[b,n,i] * W[c,n,i,o]
// ---------------------------------------------------------------------------
__global__ __launch_bounds__(256, 3) void priors_kernel(
        const float* __restrict__ x, const float* __restrict__ W) {
    __shared__ __align__(16) float sx[8][16][64];   // [n_local][b][i] 32KB

    const int c  = blockIdx.y;
    const int n0 = blockIdx.x * 8;
    const int t  = threadIdx.x;

    const float4* xg  = (const float4*)x;
    float4*       sx4 = (float4*)sx;
#pragma unroll
    for (int k = 0; k < 8; k++) {
        int j  = t + k * 256;            // 0..2047
        int i4 = j & 15;
        int b  = (j >> 4) & 15;
        int nl = j >> 8;
        sx4[(nl * 16 + b) * 16 + i4] = xg[((size_t)b * N_DIM + n0 + nl) * 16 + i4];
    }
    __syncthreads();

    const int nl   = t >> 5;
    const int lane = t & 31;
    const int n    = n0 + nl;

    const float* Wc = W + (((size_t)c * N_DIM + n) * I_DIM) * O_DIM + lane;

    ull acc[16];
#pragma unroll
    for (int b = 0; b < 16; b++) acc[b] = 0ull;

#pragma unroll
    for (int h = 0; h < 4; h++) {
        ull wd[8];
#pragma unroll
        for (int j = 0; j < 8; j++) {
            float w0 = __ldcs(Wc + (h * 16 + 2 * j)     * O_DIM);
            float w1 = __ldcs(Wc + (h * 16 + 2 * j + 1) * O_DIM);
            wd[j] = pack2(w0, w1);
        }
#pragma unroll
        for (int b = 0; b < 16; b++) {
            const ulonglong2* xb = (const ulonglong2*)(&sx[nl][b][h * 16]);
#pragma unroll
            for (int q = 0; q < 4; q++) {
                ulonglong2 xv = xb[q];
                fma2(acc[b], xv.x, wd[2 * q]);
                fma2(acc[b], xv.y, wd[2 * q + 1]);
            }
        }
    }

    float* pout = g_priors + (((size_t)c * B_DIM) * N_DIM + n) * O_DIM + lane;
#pragma unroll
    for (int b = 0; b < 16; b++) {
        float2 f = unpack2(acc[b]);
        pout[(size_t)b * N_DIM * O_DIM] = f.x + f.y;
    }
}

// ---------------------------------------------------------------------------
// Kernel 2: fused routing, one block per (c,b), 256 threads.
// Stage 128KB priors slice to smem ONCE (iter-1 column sum computed during
// the copy), then iters 2/3 run from smem with online softmax (one smem
// read each). Natural stride 32 floats: LDS.128 phases (lanes 0-7 share a
// row) are conflict-free without padding.
// ---------------------------------------------------------------------------
__global__ __launch_bounds__(256, 1) void routing_fused(float* __restrict__ out) {
    extern __shared__ __align__(16) float sm[];
    float*  P     = sm;                         // 1024*32 = 128KB
    float4* sred  = (float4*)(P + N_DIM * O_DIM);   // 256 float4 = 4KB
    float*  sm_w  = (float*)(sred + 256);       // 32
    float*  sm_m  = sm_w + 32;                  // 8
    float*  sm_z  = sm_m + 8;                   // 8
    float*  sm_acc = sm_z + 8;                  // 8*32

    const int cb = blockIdx.x;
    const int t  = threadIdx.x;
    const int l  = t & 31;
    const int w  = t >> 5;

    // ---- stage + iter-1 partial sums (thread t has fixed column group t&7) --
    const float4* gp = (const float4*)(g_priors + (size_t)cb * N_DIM * O_DIM);
    float4*       P4 = (float4*)P;
    float4 s = make_float4(0.f, 0.f, 0.f, 0.f);
#pragma unroll 8
    for (int k = 0; k < 32; k++) {
        int j = t + k * 256;                    // j = n*8 + o4, o4 = t&7
        float4 p = gp[j];
        s.x += p.x; s.y += p.y; s.z += p.z; s.w += p.w;
        P4[j] = p;
    }
    sred[t] = s;
    __syncthreads();

    // ---- out1 = squash(mean) ----
    if (t < 32) {
        int oo4 = t >> 2, c = t & 3;
        float v = 0.f;
#pragma unroll
        for (int g = 0; g < 32; g++)
            v += ((const float*)&sred[oo4 + 8 * g])[c];
        v *= (1.f / N_DIM);
        float sq = v * v;
#pragma unroll
        for (int off = 16; off; off >>= 1)
            sq += __shfl_xor_sync(~0u, sq, off);
        sm_w[t] = v * (sqrtf(sq) / (1.f + sq));
    }
    __syncthreads();

    // ---- iterations 2 and 3: online softmax from smem ----
    const int sub = l >> 3;     // row within 4-row group
    const int o4  = l & 7;      // float4 within row
    for (int it = 0; it < 2; it++) {
        float4 w4 = *(const float4*)(sm_w + o4 * 4);

        float  m = -3.0e38f, Z = 0.f;
        float4 acc = make_float4(0.f, 0.f, 0.f, 0.f);
#pragma unroll 4
        for (int r = 0; r < 32; r++) {
            int n = r * 32 + w * 4 + sub;
            float4 p = *(const float4*)(P + n * O_DIM + o4 * 4);
            float d = p.x * w4.x + p.y * w4.y + p.z * w4.z + p.w * w4.w;
            d += __shfl_xor_sync(~0u, d, 4);
            d += __shfl_xor_sync(~0u, d, 2);
            d += __shfl_xor_sync(~0u, d, 1);    // all 8 row-lanes hold full dot
            float mn = fmaxf(m, d);
            float sc = __expf(m - mn);
            float e  = __expf(d - mn);
            Z = Z * sc + e;
            acc.x = acc.x * sc + e * p.x;
            acc.y = acc.y * sc + e * p.y;
            acc.z = acc.z * sc + e * p.z;
            acc.w = acc.w * sc + e * p.w;
            m = mn;
        }

        // merge the 4 row-subgroups (lanes xor 8, 16)
#pragma unroll
        for (int off = 8; off <= 16; off <<= 1) {
            float m2 = __shfl_xor_sync(~0u, m, off);
            float Z2 = __shfl_xor_sync(~0u, Z, off);
            float ax = __shfl_xor_sync(~0u, acc.x, off);
            float ay = __shfl_xor_sync(~0u, acc.y, off);
            float az = __shfl_xor_sync(~0u, acc.z, off);
            float aw = __shfl_xor_sync(~0u, acc.w, off);
            float M  = fmaxf(m, m2);
            float s1 = __expf(m  - M);
            float s2 = __expf(m2 - M);
            Z = Z * s1 + Z2 * s2;
            acc.x = acc.x * s1 + ax * s2;
            acc.y = acc.y * s1 + ay * s2;
            acc.z = acc.z * s1 + az * s2;
            acc.w = acc.w * s1 + aw * s2;
            m = M;
        }
        if (l == 0) { sm_m[w] = m; sm_z[w] = Z; }
        if (l < 8) {
            sm_acc[w * 32 + o4 * 4 + 0] = acc.x;
            sm_acc[w * 32 + o4 * 4 + 1] = acc.y;
            sm_acc[w * 32 + o4 * 4 + 2] = acc.z;
            sm_acc[w * 32 + o4 * 4 + 3] = acc.w;
        }
        __syncthreads();

        if (t < 32) {
            float M = sm_m[0];
#pragma unroll
            for (int g = 1; g < 8; g++) M = fmaxf(M, sm_m[g]);
            float Zt = 0.f, st = 0.f;
#pragma unroll
            for (int g = 0; g < 8; g++) {
                float f = __expf(sm_m[g] - M);
                Zt += sm_z[g] * f;
                st += sm_acc[g * 32 + t] * f;
            }
            float v = st / Zt;
            float sq = v * v;
#pragma unroll
            for (int off = 16; off; off >>= 1)
                sq += __shfl_xor_sync(~0u, sq, off);
            float o = v * (sqrtf(sq) / (1.f + sq));
            if (it == 0)
                sm_w[t] += o;               // iter-3 weight = out1 + out2
            else
                out[cb * O_DIM + t] = o;
        }
        __syncthreads();
    }
}

// ---------------------------------------------------------------------------
extern "C" void kernel_launch(void* const* d_in, const int* in_sizes, int n_in,
                              void* d_out, int out_size) {
    const float* x = (const float*)d_in[0];
    const float* W = (const float*)d_in[1];
    if (n_in >= 2 && in_sizes[0] > in_sizes[1]) {  // defensive input ordering
        x = (const float*)d_in[1];
        W = (const float*)d_in[0];
    }

    // P 128KB + sred 4KB + sm_w/sm_m/sm_z/sm_acc
    const int SMEM2 = (N_DIM * O_DIM + 256 * 4 + 32 + 8 + 8 + 8 * 32) * 4;  // 136512 B
    cudaFuncSetAttribute(routing_fused,
                         cudaFuncAttributeMaxDynamicSharedMemorySize, SMEM2);

    priors_kernel<<<dim3(N_DIM / 8, C_DIM), 256>>>(x, W);
    routing_fused<<<CB, 256, SMEM2>>>((float*)d_out);
}